// round 11
// baseline (speedup 1.0000x reference)
#include <cuda_runtime.h>
#include <cstdint>
#include <cstddef>

#define Bn 128
#define Tn 2048
#define Cn 128
#define NTHR 512
#define TSTRIDE 132  // padded row stride for transposed transitions in smem (backward)

// Scratch: all forward alphas (exact fp32). __device__ global (no runtime alloc).
__device__ __align__(16) float g_alpha[(size_t)Bn * Tn * Cn];

__device__ __forceinline__ unsigned long long pack2(float lo, float hi) {
    unsigned long long r;
    asm("mov.b64 %0, {%1, %2};" : "=l"(r) : "f"(lo), "f"(hi));
    return r;
}
__device__ __forceinline__ unsigned long long add2(unsigned long long a, unsigned long long b) {
    unsigned long long r;
    asm("add.rn.f32x2 %0, %1, %2;" : "=l"(r) : "l"(a), "l"(b));
    return r;
}
__device__ __forceinline__ float lo32(unsigned long long v) {
    return __uint_as_float((unsigned)v);
}
__device__ __forceinline__ float hi32(unsigned long long v) {
    return __uint_as_float((unsigned)(v >> 32));
}

__device__ __forceinline__ float4 f4max(float4 a, float4 b) {
    return make_float4(fmaxf(a.x, b.x), fmaxf(a.y, b.y),
                       fmaxf(a.z, b.z), fmaxf(a.w, b.w));
}

// ============================ FORWARD (R8 — best known, unchanged) ============================
__global__ __launch_bounds__(NTHR, 1)
void viterbi_fwd(const float* __restrict__ pot,
                 const float* __restrict__ trans) {
    __shared__ __align__(16) float sb[2][Cn];  // double-buffered alpha row

    const int b = blockIdx.x;
    const int tid = threadIdx.x;
    const int c = tid & 3;    // i-chunk within quad
    const int j = tid >> 2;   // class handled by this thread-quad

    // Per-thread transition regs: i = 16g + 4c + {0..3}, column j, packed.
    unsigned long long tr2[16];
    #pragma unroll
    for (int g = 0; g < 8; ++g) {
        int i0 = 16 * g + 4 * c;
        float t0 = trans[(i0 + 0) * Cn + j];
        float t1 = trans[(i0 + 1) * Cn + j];
        float t2 = trans[(i0 + 2) * Cn + j];
        float t3 = trans[(i0 + 3) * Cn + j];
        tr2[2 * g]     = pack2(t0, t1);
        tr2[2 * g + 1] = pack2(t2, t3);
    }

    const float* potp = pot + (size_t)b * Tn * Cn + j;
    float* aout = g_alpha + (size_t)b * Tn * Cn + j;

    // t = 0
    if (c == 0) {
        float a0 = potp[0];
        sb[0][j] = a0;
        aout[0] = a0;
    }

    const bool pfl = (c < 2);
    float pr[4] = {0.f, 0.f, 0.f, 0.f};
    if (pfl) {
        pr[1] = potp[(size_t)1 * Cn];
        pr[2] = potp[(size_t)2 * Cn];
        pr[3] = potp[(size_t)3 * Cn];
        pr[0] = potp[(size_t)4 * Cn];
    }

    __syncthreads();

    int p = 0;

    auto step = [&](int t, bool PF) {
        float potv = pr[t & 3];
        if (PF && pfl) {
            int idx = min(t + 4, Tn - 1);                 // clamp: no guard branch
            pr[t & 3] = potp[(size_t)idx * Cn];
        }

        const ulonglong2* ab = (const ulonglong2*)sb[p];
        float g0[8];
        #pragma unroll
        for (int g = 0; g < 8; ++g) {
            ulonglong2 a = ab[4 * g + c];  // 16B: alpha[16g+4c .. +3]
            unsigned long long s01 = add2(a.x, tr2[2 * g]);
            unsigned long long s23 = add2(a.y, tr2[2 * g + 1]);
            g0[g] = fmaxf(fmaxf(lo32(s01), hi32(s01)), fmaxf(lo32(s23), hi32(s23)));
        }
        float h0 = fmaxf(g0[0], g0[1]);
        float h1 = fmaxf(g0[2], g0[3]);
        float h2 = fmaxf(g0[4], g0[5]);
        float h3 = fmaxf(g0[6], g0[7]);
        float best = fmaxf(fmaxf(h0, h1), fmaxf(h2, h3));
        best = fmaxf(best, __shfl_xor_sync(0xffffffffu, best, 1));
        best = fmaxf(best, __shfl_xor_sync(0xffffffffu, best, 2));

        float alpha = best + potv;
        if (c == 0) sb[p ^ 1][j] = alpha;           // @P STS
        if (c == 1) aout[(size_t)t * Cn] = alpha;   // @P STG (off the STS lane)
        __syncthreads();
        p ^= 1;
    };

    for (int tb = 1; tb <= Tn - 7; tb += 4) {
        step(tb + 0, true);
        step(tb + 1, true);
        step(tb + 2, true);
        step(tb + 3, true);
    }
    step(Tn - 3, false);
    step(Tn - 2, false);
    step(Tn - 1, false);
}

// ============================ BACKWARD (4 batches per warp) ============================
// Lane l: group g = l>>3 (batch-in-warp), ll = l&7. Group argmax over 128 values,
// 16 per lane (j = 16*ll + slot). Numeric-equality tie-break, lowest lane then
// lowest slot = first-occurrence argmax (matches jnp.argmax).
__device__ __forceinline__ int argmax128_grp8(const float4 s0, const float4 s1,
                                              const float4 s2, const float4 s3,
                                              int l) {
    float4 q = f4max(f4max(s0, s1), f4max(s2, s3));
    float m = fmaxf(fmaxf(q.x, q.y), fmaxf(q.z, q.w));

    // 3-level butterfly within the 8-lane group
    float wm = m;
    wm = fmaxf(wm, __shfl_xor_sync(0xffffffffu, wm, 4));
    wm = fmaxf(wm, __shfl_xor_sync(0xffffffffu, wm, 2));
    wm = fmaxf(wm, __shfl_xor_sync(0xffffffffu, wm, 1));

    // In-lane first slot equal to m (depends only on m: overlaps the butterfly).
    int i0  = (s0.x == m) ? 0  : 99;
    int i1  = (s0.y == m) ? 1  : 99;
    int i2  = (s0.z == m) ? 2  : 99;
    int i3  = (s0.w == m) ? 3  : 99;
    int i4  = (s1.x == m) ? 4  : 99;
    int i5  = (s1.y == m) ? 5  : 99;
    int i6  = (s1.z == m) ? 6  : 99;
    int i7  = (s1.w == m) ? 7  : 99;
    int i8  = (s2.x == m) ? 8  : 99;
    int i9  = (s2.y == m) ? 9  : 99;
    int i10 = (s2.z == m) ? 10 : 99;
    int i11 = (s2.w == m) ? 11 : 99;
    int i12 = (s3.x == m) ? 12 : 99;
    int i13 = (s3.y == m) ? 13 : 99;
    int i14 = (s3.z == m) ? 14 : 99;
    int i15 = (s3.w == m) ? 15 : 99;
    int loc = min(min(min(min(i0, i1), min(i2, i3)), min(min(i4, i5), min(i6, i7))),
                  min(min(min(i8, i9), min(i10, i11)), min(min(i12, i13), min(i14, i15))));

    unsigned ball = __ballot_sync(0xffffffffu, m == wm);
    int gbase = l & 24;                                  // 8 * group
    unsigned gball = (ball >> gbase) & 0xffu;
    int lanein = __ffs((int)gball) - 1;                  // lowest lane in group
    int locw = __shfl_sync(0xffffffffu, loc, gbase + lanein);
    return 16 * lanein + locw;
}

__global__ __launch_bounds__(128, 1)
void viterbi_bwd(const float* __restrict__ trans,
                 float* __restrict__ out) {
    extern __shared__ float tT[];  // [Cn][TSTRIDE]: tT[j*TSTRIDE + i] = trans[i][j]

    const int tid = threadIdx.x;

    // Build transposed transitions in smem (coalesced reads across tid).
    {
        int j0 = tid;  // 0..127
        #pragma unroll 8
        for (int i = 0; i < Cn; ++i) {
            tT[j0 * TSTRIDE + i] = trans[i * Cn + j0];
        }
    }
    __syncthreads();

    if (tid < 32) {
        const int l = tid;
        const int g = l >> 3;       // batch-in-warp
        const int ll = l & 7;       // lane-in-group
        const int b = blockIdx.x * 4 + g;
        float* ob = out + (size_t)b * Tn;
        const float4* arow = (const float4*)(g_alpha + (size_t)b * Tn * Cn);

        int tag;
        // last tag = argmax over alpha_{T-1}
        {
            size_t base = (size_t)(Tn - 1) * 32 + 4 * ll;
            float4 V0 = arow[base + 0];
            float4 V1 = arow[base + 1];
            float4 V2 = arow[base + 2];
            float4 V3 = arow[base + 3];
            tag = argmax128_grp8(V0, V1, V2, V3, l);
        }
        if (ll == 0) ob[Tn - 1] = (float)tag;

        // Prefetch ring, depth 4, slot = row & 3. Init rows 2046..2043.
        float4 pf[4][4];
        #pragma unroll
        for (int k = 0; k < 4; ++k) {
            int r = Tn - 2 - k;
            int u = r & 3;
            size_t base = (size_t)r * 32 + 4 * ll;
            pf[u][0] = arow[base + 0];
            pf[u][1] = arow[base + 1];
            pf[u][2] = arow[base + 2];
            pf[u][3] = arow[base + 3];
        }

        // Branch-free step: consume slot t&3, refill with row max(t-4, 0).
        auto tstep = [&](int t) {
            int u = t & 3;
            float4 A0 = pf[u][0], A1 = pf[u][1], A2 = pf[u][2], A3 = pf[u][3];
            size_t pidx = (size_t)max(t - 4, 0) * 32 + 4 * ll;
            pf[u][0] = arow[pidx + 0];
            pf[u][1] = arow[pidx + 1];
            pf[u][2] = arow[pidx + 2];
            pf[u][3] = arow[pidx + 3];

            const float4* trow = (const float4*)(tT + tag * TSTRIDE);
            float4 T0 = trow[4 * ll + 0];
            float4 T1 = trow[4 * ll + 1];
            float4 T2 = trow[4 * ll + 2];
            float4 T3 = trow[4 * ll + 3];

            float4 s0 = make_float4(A0.x + T0.x, A0.y + T0.y, A0.z + T0.z, A0.w + T0.w);
            float4 s1 = make_float4(A1.x + T1.x, A1.y + T1.y, A1.z + T1.z, A1.w + T1.w);
            float4 s2 = make_float4(A2.x + T2.x, A2.y + T2.y, A2.z + T2.z, A2.w + T2.w);
            float4 s3 = make_float4(A3.x + T3.x, A3.y + T3.y, A3.z + T3.z, A3.w + T3.w);

            tag = argmax128_grp8(s0, s1, s2, s3, l);
            if (ll == 0) ob[t] = (float)tag;   // @P STG (one lane per group)
        };

        // Main: t = 2046 .. 3 (511 branch-free blocks of 4).
        for (int tb = Tn - 2; tb >= 6; tb -= 4) {
            tstep(tb - 0);
            tstep(tb - 1);
            tstep(tb - 2);
            tstep(tb - 3);
        }
        // Tail: t = 2, 1, 0 (slots already hold rows 2, 1, 0).
        tstep(2);
        tstep(1);
        tstep(0);
    }
}

extern "C" void kernel_launch(void* const* d_in, const int* in_sizes, int n_in,
                              void* d_out, int out_size) {
    const float* inputs = (const float*)d_in[0];       // [B, T, C] f32
    const float* transitions = (const float*)d_in[1];  // [C, C] f32
    float* out = (float*)d_out;                        // [B, T] f32 (tags)

    viterbi_fwd<<<Bn, NTHR>>>(inputs, transitions);

    const int bwd_smem = Cn * TSTRIDE * (int)sizeof(float);  // ~67.6KB
    cudaFuncSetAttribute(viterbi_bwd, cudaFuncAttributeMaxDynamicSharedMemorySize, bwd_smem);
    viterbi_bwd<<<Bn / 4, 128, bwd_smem>>>(transitions, out);
}

// round 12
// speedup vs baseline: 2.3108x; 2.3108x over previous
#include <cuda_runtime.h>
#include <cstdint>
#include <cstddef>

#define Bn 128
#define Tn 2048
#define Cn 128
#define TSTRIDE 132  // padded row stride for transposed transitions in smem (backward)

// Scratch: all forward alphas (exact fp32). __device__ global (no runtime alloc).
__device__ __align__(16) float g_alpha[(size_t)Bn * Tn * Cn];

__device__ __forceinline__ unsigned long long pack2(float lo, float hi) {
    unsigned long long r;
    asm("mov.b64 %0, {%1, %2};" : "=l"(r) : "f"(lo), "f"(hi));
    return r;
}
__device__ __forceinline__ unsigned long long add2(unsigned long long a, unsigned long long b) {
    unsigned long long r;
    asm("add.rn.f32x2 %0, %1, %2;" : "=l"(r) : "l"(a), "l"(b));
    return r;
}
__device__ __forceinline__ float lo32(unsigned long long v) {
    return __uint_as_float((unsigned)v);
}
__device__ __forceinline__ float hi32(unsigned long long v) {
    return __uint_as_float((unsigned)(v >> 32));
}

__device__ __forceinline__ float4 f4max(float4 a, float4 b) {
    return make_float4(fmaxf(a.x, b.x), fmaxf(a.y, b.y),
                       fmaxf(a.z, b.z), fmaxf(a.w, b.w));
}

// ============================ FORWARD ============================
// 128 threads, 1 class j per thread, all 128 i's in-thread (NO shuffles in hot loop).
// 8 rotating max accumulators keep the dependent chain shallow (~depth 4 + trees).
__global__ __launch_bounds__(128, 1)
void viterbi_fwd(const float* __restrict__ pot,
                 const float* __restrict__ trans) {
    __shared__ __align__(16) float sb[2][Cn];  // double-buffered alpha row

    const int b = blockIdx.x;
    const int j = threadIdx.x;

    // Transition column j in registers, packed: tr2[q] = (T[2q][j], T[2q+1][j]).
    unsigned long long tr2[64];
    #pragma unroll
    for (int q = 0; q < 64; ++q) {
        tr2[q] = pack2(trans[(2 * q) * Cn + j], trans[(2 * q + 1) * Cn + j]);
    }

    const float* potp = pot + (size_t)b * Tn * Cn + j;
    float* aout = g_alpha + (size_t)b * Tn * Cn + j;

    // t = 0
    {
        float a0 = potp[0];
        sb[0][j] = a0;
        aout[0] = a0;
    }

    // Potentials prefetch ring (distance 4), clamped refills: branch-free forever.
    float pr[4];
    pr[1] = potp[(size_t)1 * Cn];
    pr[2] = potp[(size_t)2 * Cn];
    pr[3] = potp[(size_t)3 * Cn];
    pr[0] = potp[(size_t)4 * Cn];

    __syncthreads();

    int p = 0;

    auto step = [&](int t, bool PF) {
        float potv = pr[t & 3];
        if (PF) {
            pr[t & 3] = potp[(size_t)min(t + 4, Tn - 1) * Cn];
        }

        const ulonglong2* ab = (const ulonglong2*)sb[p];
        float m[8];
        #pragma unroll
        for (int g = 0; g < 32; ++g) {
            ulonglong2 A = ab[g];  // broadcast LDS.128: alphas[4g .. 4g+3]
            unsigned long long s01 = add2(A.x, tr2[2 * g]);
            unsigned long long s23 = add2(A.y, tr2[2 * g + 1]);
            float q = fmaxf(fmaxf(lo32(s01), hi32(s01)), fmaxf(lo32(s23), hi32(s23)));
            if (g < 8) m[g] = q;                 // init (compile-time)
            else       m[g & 7] = fmaxf(m[g & 7], q);
        }
        float h0 = fmaxf(m[0], m[1]);
        float h1 = fmaxf(m[2], m[3]);
        float h2 = fmaxf(m[4], m[5]);
        float h3 = fmaxf(m[6], m[7]);
        float best = fmaxf(fmaxf(h0, h1), fmaxf(h2, h3));

        float alpha = best + potv;
        sb[p ^ 1][j] = alpha;               // STS (all 128 threads, conflict-free)
        aout[(size_t)t * Cn] = alpha;       // STG archive (coalesced 512B)
        __syncthreads();
        p ^= 1;
    };

    // Main: t = 1 .. 2044 (511 branch-free blocks of 4), tail 3 steps.
    for (int tb = 1; tb <= Tn - 7; tb += 4) {
        step(tb + 0, true);
        step(tb + 1, true);
        step(tb + 2, true);
        step(tb + 3, true);
    }
    step(Tn - 3, false);
    step(Tn - 2, false);
    step(Tn - 1, false);
}

// ============================ BACKWARD ============================
// Warp argmax over 128 values (lane l holds indices 4l..4l+3) via double-buffered
// smem broadcast reduce — NO shuffle butterfly. Numeric-equality tie-break, lowest
// lane then lowest slot = first-occurrence (matches jnp.argmax; validated R9).
__device__ __forceinline__ int warp_argmax4_smem(float4 v, int l, float* pad) {
    float m = fmaxf(fmaxf(v.x, v.y), fmaxf(v.z, v.w));
    pad[l] = m;
    __syncwarp();
    const float4* p4 = (const float4*)pad;
    float4 a = f4max(f4max(p4[0], p4[1]), f4max(p4[2], p4[3]));
    float4 c = f4max(a, f4max(f4max(p4[4], p4[5]), f4max(p4[6], p4[7])));
    float wm = fmaxf(fmaxf(c.x, c.y), fmaxf(c.z, c.w));

    // Lane-local first slot equal to m (depends only on m: overlaps the reduce).
    int loc = (v.x == m) ? 0 : ((v.y == m) ? 1 : ((v.z == m) ? 2 : 3));

    unsigned ball = __ballot_sync(0xffffffffu, m == wm);
    int lane = __ffs(ball) - 1;
    int locw = __shfl_sync(0xffffffffu, loc, lane);
    return 4 * lane + locw;
}

__global__ __launch_bounds__(128, 1)
void viterbi_bwd(const float* __restrict__ trans,
                 float* __restrict__ out) {
    extern __shared__ float smem[];
    float* tT = smem;                         // [Cn][TSTRIDE]
    float* pad = smem + Cn * TSTRIDE;         // [2][32] double-buffered partials

    const int b = blockIdx.x;
    const int tid = threadIdx.x;

    // Build transposed transitions in smem (coalesced reads across tid).
    {
        int j0 = tid;  // 0..127
        #pragma unroll 8
        for (int i = 0; i < Cn; ++i) {
            tT[j0 * TSTRIDE + i] = trans[i * Cn + j0];
        }
    }
    __syncthreads();

    if (tid < 32) {
        const int l = tid;
        float* ob = out + (size_t)b * Tn;
        const float4* arow = (const float4*)(g_alpha + (size_t)b * Tn * Cn);

        int tag;
        // last tag = argmax over alpha_{T-1}; pad parity = (Tn-1)&1 = 1.
        {
            float4 av = arow[(size_t)(Tn - 1) * 32 + l];
            tag = warp_argmax4_smem(av, l, pad + 32);
        }
        if (l == 0) ob[Tn - 1] = (float)tag;

        // Prefetch alpha rows 8 deep: pf[u] = row (2046 - u).
        float4 pf[8];
        #pragma unroll
        for (int u = 0; u < 8; ++u) {
            pf[u] = arow[(size_t)(Tn - 2 - u) * 32 + l];
        }

        // One trace step; PF=true: unconditional prefetch of row t-8 (in range);
        // PF=false: clamped prefetch, still branch-free. pad parity = t&1
        // (double buffer: write of step t can't race reads of step t-1).
        auto tstep = [&](int t, int u, bool PF) {
            float4 a = pf[u];
            if (PF) {
                pf[u] = arow[(size_t)(t - 8) * 32 + l];
            } else {
                int idx = max(t - 8, 0);
                pf[u] = arow[(size_t)idx * 32 + l];
            }
            const float4* trow = (const float4*)(tT + tag * TSTRIDE);
            float4 tv = trow[l];
            float4 s;
            s.x = a.x + tv.x;
            s.y = a.y + tv.y;
            s.z = a.z + tv.z;
            s.w = a.w + tv.w;
            tag = warp_argmax4_smem(s, l, pad + (t & 1) * 32);
            if (l == 0) ob[t] = (float)tag;              // @P STG
        };

        // Main: t = 2046 .. 15 (254 blocks of 8, fully branch-free).
        for (int tb = Tn - 2; tb >= 22; tb -= 8) {
            #pragma unroll
            for (int u = 0; u < 8; ++u) {
                tstep(tb - u, u, true);
            }
        }
        // Tail A: t = 14 .. 7 (clamped prefetch fills rows 6..0 into pf[0..6]).
        #pragma unroll
        for (int u = 0; u < 8; ++u) {
            tstep(14 - u, u, false);
        }
        // Tail B: t = 6 .. 0 (pf[0..6] hold rows 6..0).
        #pragma unroll
        for (int u = 0; u < 7; ++u) {
            int t = 6 - u;
            float4 a = pf[u];
            const float4* trow = (const float4*)(tT + tag * TSTRIDE);
            float4 tv = trow[l];
            float4 s;
            s.x = a.x + tv.x;
            s.y = a.y + tv.y;
            s.z = a.z + tv.z;
            s.w = a.w + tv.w;
            tag = warp_argmax4_smem(s, l, pad + (t & 1) * 32);
            if (l == 0) ob[t] = (float)tag;
        }
    }
}

extern "C" void kernel_launch(void* const* d_in, const int* in_sizes, int n_in,
                              void* d_out, int out_size) {
    const float* inputs = (const float*)d_in[0];       // [B, T, C] f32
    const float* transitions = (const float*)d_in[1];  // [C, C] f32
    float* out = (float*)d_out;                        // [B, T] f32 (tags)

    viterbi_fwd<<<Bn, 128>>>(inputs, transitions);

    const int bwd_smem = (Cn * TSTRIDE + 64) * (int)sizeof(float);  // ~67.8KB
    cudaFuncSetAttribute(viterbi_bwd, cudaFuncAttributeMaxDynamicSharedMemorySize, bwd_smem);
    viterbi_bwd<<<Bn, 128, bwd_smem>>>(transitions, out);
}